// round 12
// baseline (speedup 1.0000x reference)
#include <cuda_runtime.h>
#include <math.h>
#include <stdint.h>

#define N_NODES 100000
#define D_FEAT  64
#define N_EDGES 1250000

#define IN_VEC_STRIDE  16   // 64 floats = 16 float4
#define OUT_VEC_STRIDE 32   // 128 floats = 32 float4
#define BKT_CAP        64   // Poisson(12.5): P(deg>63) ~ 1e-25

// ---- static scratch ----
// Zero-initialized at module load; node_max resets g_cnt after reading, so the
// "counters are zero at kernel_launch entry" invariant holds on every call.
__device__ __align__(16) int g_cnt[N_NODES];
__device__ __align__(16) int g_bkt[(size_t)N_NODES * BKT_CAP];   // 25.6 MB

// K1a: bucket fill, 8 edges/thread via 2x int4 loads (16B-aligned src/dst)
__global__ void fill_kernel_vec(const int4* __restrict__ src4,
                                const int4* __restrict__ dst4) {
    int t = blockIdx.x * blockDim.x + threadIdx.x;
    if (t >= N_EDGES / 8) return;
    int4 sA = src4[t * 2],     dA = dst4[t * 2];
    int4 sB = src4[t * 2 + 1], dB = dst4[t * 2 + 1];
    int p;
    p = atomicAdd(&g_cnt[dA.x], 1); if (p < BKT_CAP) g_bkt[(size_t)dA.x * BKT_CAP + p] = sA.x;
    p = atomicAdd(&g_cnt[dA.y], 1); if (p < BKT_CAP) g_bkt[(size_t)dA.y * BKT_CAP + p] = sA.y;
    p = atomicAdd(&g_cnt[dA.z], 1); if (p < BKT_CAP) g_bkt[(size_t)dA.z * BKT_CAP + p] = sA.z;
    p = atomicAdd(&g_cnt[dA.w], 1); if (p < BKT_CAP) g_bkt[(size_t)dA.w * BKT_CAP + p] = sA.w;
    p = atomicAdd(&g_cnt[dB.x], 1); if (p < BKT_CAP) g_bkt[(size_t)dB.x * BKT_CAP + p] = sB.x;
    p = atomicAdd(&g_cnt[dB.y], 1); if (p < BKT_CAP) g_bkt[(size_t)dB.y * BKT_CAP + p] = sB.y;
    p = atomicAdd(&g_cnt[dB.z], 1); if (p < BKT_CAP) g_bkt[(size_t)dB.z * BKT_CAP + p] = sB.z;
    p = atomicAdd(&g_cnt[dB.w], 1); if (p < BKT_CAP) g_bkt[(size_t)dB.w * BKT_CAP + p] = sB.w;
}

// K1b: scalar fallback, 4 edges/thread
__global__ void fill_kernel_scalar(const int* __restrict__ src,
                                   const int* __restrict__ dst) {
    int t = blockIdx.x * blockDim.x + threadIdx.x;
    int e = t * 4;
    if (e >= N_EDGES) return;
    int d0 = dst[e], d1 = dst[e+1], d2 = dst[e+2], d3 = dst[e+3];
    int s0 = src[e], s1 = src[e+1], s2 = src[e+2], s3 = src[e+3];
    int p0 = atomicAdd(&g_cnt[d0], 1);
    int p1 = atomicAdd(&g_cnt[d1], 1);
    int p2 = atomicAdd(&g_cnt[d2], 1);
    int p3 = atomicAdd(&g_cnt[d3], 1);
    if (p0 < BKT_CAP) g_bkt[(size_t)d0 * BKT_CAP + p0] = s0;
    if (p1 < BKT_CAP) g_bkt[(size_t)d1 * BKT_CAP + p1] = s1;
    if (p2 < BKT_CAP) g_bkt[(size_t)d2 * BKT_CAP + p2] = s2;
    if (p3 < BKT_CAP) g_bkt[(size_t)d3 * BKT_CAP + p3] = s3;
}

__device__ __forceinline__ void fmax4(float4& acc, const float4& v) {
    acc.x = fmaxf(acc.x, v.x); acc.y = fmaxf(acc.y, v.y);
    acc.z = fmaxf(acc.z, v.z); acc.w = fmaxf(acc.w, v.w);
}

// K2: one WARP per node. Fast path (deg <= 32, ~all nodes): main loop runs
// FULL 8-edge iterations with no predication (4 in-flight gathers per lane),
// then one predicated 8-wide tail iter. Rare path (deg > 32, P~1e-5): general
// two-half loop. Warp-uniform bounds keep all shfls full-warp legal.
__global__ void __launch_bounds__(256) node_max_kernel(
        const float4* __restrict__ in4,
        float4*       __restrict__ out4) {
    int tid  = threadIdx.x;
    int lane = tid & 31;
    int g    = lane & 15;                      // float4 feature group
    int h    = lane >> 4;                      // half 0/1
    int node = blockIdx.x * 8 + (tid >> 5);    // 12500 * 8 = 100000 exact

    int deg = g_cnt[node];
    if (lane == 0) g_cnt[node] = 0;            // restore invariant for next call
    if (deg > BKT_CAP) deg = BKT_CAP;
    const int* __restrict__ bkt = g_bkt + (size_t)node * BKT_CAP;

    const unsigned FULL = 0xFFFFFFFFu;
    int idxA = (lane < deg) ? __ldg(&bkt[lane]) : 0;

    float4 own = __ldg(&in4[(size_t)node * IN_VEC_STRIDE + g]);

    float4 acc = make_float4(-INFINITY, -INFINITY, -INFINITY, -INFINITY);

    if (deg <= 32) {
        int eb = 0;
        // full iterations: 8 edges, no predication, 4 gathers in flight/lane
        for (; eb + 8 <= deg; eb += 8) {
            int s0 = __shfl_sync(FULL, idxA, eb + h);
            int s1 = __shfl_sync(FULL, idxA, eb + 2 + h);
            int s2 = __shfl_sync(FULL, idxA, eb + 4 + h);
            int s3 = __shfl_sync(FULL, idxA, eb + 6 + h);
            float4 v0 = __ldg(&in4[(size_t)s0 * IN_VEC_STRIDE + g]);
            float4 v1 = __ldg(&in4[(size_t)s1 * IN_VEC_STRIDE + g]);
            float4 v2 = __ldg(&in4[(size_t)s2 * IN_VEC_STRIDE + g]);
            float4 v3 = __ldg(&in4[(size_t)s3 * IN_VEC_STRIDE + g]);
            fmax4(acc, v0); fmax4(acc, v1); fmax4(acc, v2); fmax4(acc, v3);
        }
        // tail: up to 7 edges, one predicated 8-wide iter
        if (eb < deg) {
            int e0 = eb + h,     e1 = eb + 2 + h;
            int e2 = eb + 4 + h, e3 = eb + 6 + h;
            int s0 = __shfl_sync(FULL, idxA, e0 & 31);
            int s1 = __shfl_sync(FULL, idxA, e1 & 31);
            int s2 = __shfl_sync(FULL, idxA, e2 & 31);
            int s3 = __shfl_sync(FULL, idxA, e3 & 31);
            if (e0 < deg) fmax4(acc, __ldg(&in4[(size_t)s0 * IN_VEC_STRIDE + g]));
            if (e1 < deg) fmax4(acc, __ldg(&in4[(size_t)s1 * IN_VEC_STRIDE + g]));
            if (e2 < deg) fmax4(acc, __ldg(&in4[(size_t)s2 * IN_VEC_STRIDE + g]));
            if (e3 < deg) fmax4(acc, __ldg(&in4[(size_t)s3 * IN_VEC_STRIDE + g]));
        }
    } else {
        // rare path (~1 warp in 12500): general two-half loop
        int idxB = (lane + 32 < deg) ? __ldg(&bkt[lane + 32]) : 0;
        for (int eb = 0; eb < deg; eb += 4) {
            int idx = (eb < 32) ? idxA : idxB;
            int e0 = eb + h;
            int e1 = eb + 2 + h;
            int s0 = __shfl_sync(FULL, idx, e0 & 31);
            int s1 = __shfl_sync(FULL, idx, e1 & 31);
            if (e0 < deg) fmax4(acc, __ldg(&in4[(size_t)s0 * IN_VEC_STRIDE + g]));
            if (e1 < deg) fmax4(acc, __ldg(&in4[(size_t)s1 * IN_VEC_STRIDE + g]));
        }
    }

    // combine halves (warp reconverged): 64-bit xor-shuffles
    unsigned long long acc01, acc23;
    asm("mov.b64 %0, {%1, %2};" : "=l"(acc01) : "f"(acc.x), "f"(acc.y));
    asm("mov.b64 %0, {%1, %2};" : "=l"(acc23) : "f"(acc.z), "f"(acc.w));
    unsigned long long o01 = __shfl_xor_sync(FULL, acc01, 16);
    unsigned long long o23 = __shfl_xor_sync(FULL, acc23, 16);
    float ox, oy, oz, ow;
    asm("mov.b64 {%0, %1}, %2;" : "=f"(ox), "=f"(oy) : "l"(o01));
    asm("mov.b64 {%0, %1}, %2;" : "=f"(oz), "=f"(ow) : "l"(o23));
    acc.x = fmaxf(acc.x, ox);
    acc.y = fmaxf(acc.y, oy);
    acc.z = fmaxf(acc.z, oz);
    acc.w = fmaxf(acc.w, ow);

    if (deg == 0) acc = own;   // isolated node keeps its own feature

    if (h == 1) {
        out4[(size_t)node * OUT_VEC_STRIDE + g] = own;                  // concat half
    } else {
        out4[(size_t)node * OUT_VEC_STRIDE + IN_VEC_STRIDE + g] = acc;  // agg half
    }
}

extern "C" void kernel_launch(void* const* d_in, const int* in_sizes, int n_in,
                              void* d_out, int out_size) {
    const float* inputs = (const float*)d_in[0];
    const int*   src    = (const int*)d_in[1];
    const int*   dst    = (const int*)d_in[2];
    float*       out    = (float*)d_out;
    (void)in_sizes; (void)n_in; (void)out_size;

    const int T = 256;
    bool aligned = ((((uintptr_t)src) | ((uintptr_t)dst)) & 15) == 0;
    if (aligned) {
        int blocks = (N_EDGES / 8 + T - 1) / T;
        fill_kernel_vec<<<blocks, T>>>((const int4*)src, (const int4*)dst);
    } else {
        int blocks = (N_EDGES / 4 + T - 1) / T;
        fill_kernel_scalar<<<blocks, T>>>(src, dst);
    }

    node_max_kernel<<<N_NODES / 8, T>>>((const float4*)inputs, (float4*)out);
}

// round 13
// speedup vs baseline: 1.0999x; 1.0999x over previous
#include <cuda_runtime.h>
#include <math.h>
#include <stdint.h>

#define N_NODES 100000
#define D_FEAT  64
#define N_EDGES 1250000

#define IN_VEC_STRIDE  16   // 64 floats = 16 float4
#define OUT_VEC_STRIDE 32   // 128 floats = 32 float4
#define BKT_CAP        64   // Poisson(12.5): P(deg>63) ~ 1e-25

// ---- static scratch ----
// Zero-initialized at module load; node_max resets g_cnt after reading, so the
// "counters are zero at kernel_launch entry" invariant holds on every call.
__device__ __align__(16) int g_cnt[N_NODES];
__device__ __align__(16) int g_bkt[(size_t)N_NODES * BKT_CAP];   // 25.6 MB

// K1a: bucket fill, 8 edges/thread via 2x int4 loads (16B-aligned src/dst)
__global__ void fill_kernel_vec(const int4* __restrict__ src4,
                                const int4* __restrict__ dst4) {
    int t = blockIdx.x * blockDim.x + threadIdx.x;
    if (t >= N_EDGES / 8) return;
    int4 sA = src4[t * 2],     dA = dst4[t * 2];
    int4 sB = src4[t * 2 + 1], dB = dst4[t * 2 + 1];
    int p;
    p = atomicAdd(&g_cnt[dA.x], 1); if (p < BKT_CAP) g_bkt[(size_t)dA.x * BKT_CAP + p] = sA.x;
    p = atomicAdd(&g_cnt[dA.y], 1); if (p < BKT_CAP) g_bkt[(size_t)dA.y * BKT_CAP + p] = sA.y;
    p = atomicAdd(&g_cnt[dA.z], 1); if (p < BKT_CAP) g_bkt[(size_t)dA.z * BKT_CAP + p] = sA.z;
    p = atomicAdd(&g_cnt[dA.w], 1); if (p < BKT_CAP) g_bkt[(size_t)dA.w * BKT_CAP + p] = sA.w;
    p = atomicAdd(&g_cnt[dB.x], 1); if (p < BKT_CAP) g_bkt[(size_t)dB.x * BKT_CAP + p] = sB.x;
    p = atomicAdd(&g_cnt[dB.y], 1); if (p < BKT_CAP) g_bkt[(size_t)dB.y * BKT_CAP + p] = sB.y;
    p = atomicAdd(&g_cnt[dB.z], 1); if (p < BKT_CAP) g_bkt[(size_t)dB.z * BKT_CAP + p] = sB.z;
    p = atomicAdd(&g_cnt[dB.w], 1); if (p < BKT_CAP) g_bkt[(size_t)dB.w * BKT_CAP + p] = sB.w;
}

// K1b: scalar fallback, 4 edges/thread
__global__ void fill_kernel_scalar(const int* __restrict__ src,
                                   const int* __restrict__ dst) {
    int t = blockIdx.x * blockDim.x + threadIdx.x;
    int e = t * 4;
    if (e >= N_EDGES) return;
    int d0 = dst[e], d1 = dst[e+1], d2 = dst[e+2], d3 = dst[e+3];
    int s0 = src[e], s1 = src[e+1], s2 = src[e+2], s3 = src[e+3];
    int p0 = atomicAdd(&g_cnt[d0], 1);
    int p1 = atomicAdd(&g_cnt[d1], 1);
    int p2 = atomicAdd(&g_cnt[d2], 1);
    int p3 = atomicAdd(&g_cnt[d3], 1);
    if (p0 < BKT_CAP) g_bkt[(size_t)d0 * BKT_CAP + p0] = s0;
    if (p1 < BKT_CAP) g_bkt[(size_t)d1 * BKT_CAP + p1] = s1;
    if (p2 < BKT_CAP) g_bkt[(size_t)d2 * BKT_CAP + p2] = s2;
    if (p3 < BKT_CAP) g_bkt[(size_t)d3 * BKT_CAP + p3] = s3;
}

__device__ __forceinline__ void fmax4(float4& acc, const float4& v) {
    acc.x = fmaxf(acc.x, v.x); acc.y = fmaxf(acc.y, v.y);
    acc.z = fmaxf(acc.z, v.z); acc.w = fmaxf(acc.w, v.w);
}

// K2: one WARP per node. Fast path (deg <= 32, ~all nodes): 4-edge main iters
// with NO per-edge predication, single predicated 4-wide tail. Since deg <= 32
// and tail eb <= 28, all shuffle indices <= 31 (no masking). Rare path
// (deg > 32, P ~ 1e-5): general two-half loop. Warp-uniform loop bounds keep
// every shfl full-warp legal.
__global__ void __launch_bounds__(256) node_max_kernel(
        const float4* __restrict__ in4,
        float4*       __restrict__ out4) {
    int tid  = threadIdx.x;
    int lane = tid & 31;
    int g    = lane & 15;                      // float4 feature group
    int h    = lane >> 4;                      // half 0/1
    int node = blockIdx.x * 8 + (tid >> 5);    // 12500 * 8 = 100000 exact

    int deg = g_cnt[node];
    if (lane == 0) g_cnt[node] = 0;            // restore invariant for next call
    if (deg > BKT_CAP) deg = BKT_CAP;
    const int* __restrict__ bkt = g_bkt + (size_t)node * BKT_CAP;

    const unsigned FULL = 0xFFFFFFFFu;
    int idxA = (lane < deg) ? __ldg(&bkt[lane]) : 0;

    float4 own = __ldg(&in4[(size_t)node * IN_VEC_STRIDE + g]);
    if (h == 1) {
        // concat half: issue early so the store drains under the gather loop
        out4[(size_t)node * OUT_VEC_STRIDE + g] = own;
    }

    float4 acc = make_float4(-INFINITY, -INFINITY, -INFINITY, -INFINITY);

    if (deg <= 32) {
        int eb = 0;
        // full iterations: 4 edges, no predication
        for (; eb + 4 <= deg; eb += 4) {
            int s0 = __shfl_sync(FULL, idxA, eb + h);
            int s1 = __shfl_sync(FULL, idxA, eb + 2 + h);
            float4 v0 = __ldg(&in4[(size_t)s0 * IN_VEC_STRIDE + g]);
            float4 v1 = __ldg(&in4[(size_t)s1 * IN_VEC_STRIDE + g]);
            fmax4(acc, v0);
            fmax4(acc, v1);
        }
        // tail: 1..3 edges, one predicated iter (indices <= 31, no masking)
        if (eb < deg) {
            int e0 = eb + h;
            int e1 = eb + 2 + h;
            int s0 = __shfl_sync(FULL, idxA, e0);
            int s1 = __shfl_sync(FULL, idxA, e1);
            if (e0 < deg) fmax4(acc, __ldg(&in4[(size_t)s0 * IN_VEC_STRIDE + g]));
            if (e1 < deg) fmax4(acc, __ldg(&in4[(size_t)s1 * IN_VEC_STRIDE + g]));
        }
    } else {
        // rare path (~1 warp in 12500): general two-half loop
        int idxB = (lane + 32 < deg) ? __ldg(&bkt[lane + 32]) : 0;
        for (int eb = 0; eb < deg; eb += 4) {
            int idx = (eb < 32) ? idxA : idxB;
            int e0 = eb + h;
            int e1 = eb + 2 + h;
            int s0 = __shfl_sync(FULL, idx, e0 & 31);
            int s1 = __shfl_sync(FULL, idx, e1 & 31);
            if (e0 < deg) fmax4(acc, __ldg(&in4[(size_t)s0 * IN_VEC_STRIDE + g]));
            if (e1 < deg) fmax4(acc, __ldg(&in4[(size_t)s1 * IN_VEC_STRIDE + g]));
        }
    }

    // combine halves (warp reconverged): 64-bit xor-shuffles
    unsigned long long acc01, acc23;
    asm("mov.b64 %0, {%1, %2};" : "=l"(acc01) : "f"(acc.x), "f"(acc.y));
    asm("mov.b64 %0, {%1, %2};" : "=l"(acc23) : "f"(acc.z), "f"(acc.w));
    unsigned long long o01 = __shfl_xor_sync(FULL, acc01, 16);
    unsigned long long o23 = __shfl_xor_sync(FULL, acc23, 16);
    float ox, oy, oz, ow;
    asm("mov.b64 {%0, %1}, %2;" : "=f"(ox), "=f"(oy) : "l"(o01));
    asm("mov.b64 {%0, %1}, %2;" : "=f"(oz), "=f"(ow) : "l"(o23));
    acc.x = fmaxf(acc.x, ox);
    acc.y = fmaxf(acc.y, oy);
    acc.z = fmaxf(acc.z, oz);
    acc.w = fmaxf(acc.w, ow);

    if (deg == 0) acc = own;   // isolated node keeps its own feature

    if (h == 0) {
        out4[(size_t)node * OUT_VEC_STRIDE + IN_VEC_STRIDE + g] = acc;  // agg half
    }
}

extern "C" void kernel_launch(void* const* d_in, const int* in_sizes, int n_in,
                              void* d_out, int out_size) {
    const float* inputs = (const float*)d_in[0];
    const int*   src    = (const int*)d_in[1];
    const int*   dst    = (const int*)d_in[2];
    float*       out    = (float*)d_out;
    (void)in_sizes; (void)n_in; (void)out_size;

    const int T = 256;
    bool aligned = ((((uintptr_t)src) | ((uintptr_t)dst)) & 15) == 0;
    if (aligned) {
        int blocks = (N_EDGES / 8 + T - 1) / T;
        fill_kernel_vec<<<blocks, T>>>((const int4*)src, (const int4*)dst);
    } else {
        int blocks = (N_EDGES / 4 + T - 1) / T;
        fill_kernel_scalar<<<blocks, T>>>(src, dst);
    }

    node_max_kernel<<<N_NODES / 8, T>>>((const float4*)inputs, (float4*)out);
}